// round 14
// baseline (speedup 1.0000x reference)
#include <cuda_runtime.h>
#include <cuda_fp16.h>
#include <math.h>

#define NMAX 100000
#define EMAX 3200000
#define DIMF 128
#define SROW (DIMF + 8)   // padded smem row (halves)

// ---------------- scratch ----------------------------------------------------
__device__ __align__(16) __half g_h16[(size_t)NMAX * DIMF];  // GEMM out (gathered)
__device__ __align__(16) __half g_b16[(size_t)NMAX * DIMF];  // agg1 out (GEMM2 in)
__device__ __align__(16) __half g_W1h[DIMF * DIMF];
__device__ __align__(16) __half g_W2h[DIMF * DIMF];
__device__ __align__(16) int    g_deg[NMAX];
__device__ __align__(16) float  g_dinv[NMAX];
__device__ __align__(16) int    g_rowptr[NMAX + 1];
__device__ __align__(16) int    g_bsums[512];
__device__ __align__(16) int    g_ctr[2];                    // work-steal counters
__device__ __align__(16) unsigned long long g_edge[EMAX];    // {ws_bits:32 | col:32}

// ---------------- mma / ldmatrix helpers --------------------------------------
__device__ __forceinline__ unsigned su32(const void* p) {
    return (unsigned)__cvta_generic_to_shared(p);
}
__device__ __forceinline__ void ldsm4(unsigned& r0, unsigned& r1, unsigned& r2,
                                      unsigned& r3, unsigned addr) {
    asm volatile("ldmatrix.sync.aligned.m8n8.x4.shared.b16 {%0,%1,%2,%3}, [%4];"
                 : "=r"(r0), "=r"(r1), "=r"(r2), "=r"(r3) : "r"(addr));
}
__device__ __forceinline__ void ldsm4t(unsigned& r0, unsigned& r1, unsigned& r2,
                                       unsigned& r3, unsigned addr) {
    asm volatile("ldmatrix.sync.aligned.m8n8.x4.trans.shared.b16 {%0,%1,%2,%3}, [%4];"
                 : "=r"(r0), "=r"(r1), "=r"(r2), "=r"(r3) : "r"(addr));
}
__device__ __forceinline__ void mma16816(float* d, unsigned a0, unsigned a1,
                                         unsigned a2, unsigned a3,
                                         unsigned b0, unsigned b1) {
    asm volatile("mma.sync.aligned.m16n8k16.row.col.f32.f16.f16.f32 "
                 "{%0,%1,%2,%3},{%4,%5,%6,%7},{%8,%9},{%0,%1,%2,%3};"
                 : "+f"(d[0]), "+f"(d[1]), "+f"(d[2]), "+f"(d[3])
                 : "r"(a0), "r"(a1), "r"(a2), "r"(a3), "r"(b0), "r"(b1));
}

// ---------------- CSR build ----------------------------------------------------
__global__ void k_hist(const int* __restrict__ dst, int E, int* __restrict__ deg) {
    int e = blockIdx.x * blockDim.x + threadIdx.x;
    if (e < E) atomicAdd(&deg[dst[e]], 1);
}
__global__ void k_scan1(const int* __restrict__ in, int* __restrict__ out,
                        int* __restrict__ bsums, float* __restrict__ dinv, int n) {
    __shared__ int wsum[8];
    int tid  = threadIdx.x;
    int base = blockIdx.x * 1024 + tid * 4;
    int v0 = 0, v1 = 0, v2 = 0, v3 = 0;
    if (base + 0 < n) v0 = in[base + 0];
    if (base + 1 < n) v1 = in[base + 1];
    if (base + 2 < n) v2 = in[base + 2];
    if (base + 3 < n) v3 = in[base + 3];
    if (base + 0 < n) dinv[base + 0] = rsqrtf((float)(v0 + 1));
    if (base + 1 < n) dinv[base + 1] = rsqrtf((float)(v1 + 1));
    if (base + 2 < n) dinv[base + 2] = rsqrtf((float)(v2 + 1));
    if (base + 3 < n) dinv[base + 3] = rsqrtf((float)(v3 + 1));
    int s = v0 + v1 + v2 + v3;
    int lane = tid & 31, wid = tid >> 5;
    int inc = s;
    #pragma unroll
    for (int o = 1; o < 32; o <<= 1) {
        int t = __shfl_up_sync(0xffffffffu, inc, o);
        if (lane >= o) inc += t;
    }
    if (lane == 31) wsum[wid] = inc;
    __syncthreads();
    if (tid == 0) {
        int run = 0;
        #pragma unroll
        for (int i = 0; i < 8; i++) { int t = wsum[i]; wsum[i] = run; run += t; }
        bsums[blockIdx.x] = run;
    }
    __syncthreads();
    int ex = wsum[wid] + inc - s;
    if (base + 0 < n) out[base + 0] = ex;
    if (base + 1 < n) out[base + 1] = ex + v0;
    if (base + 2 < n) out[base + 2] = ex + v0 + v1;
    if (base + 3 < n) out[base + 3] = ex + v0 + v1 + v2;
}
__global__ void k_scan2(int* __restrict__ bsums, int nb) {
    __shared__ int wsum[4];
    int tid = threadIdx.x;
    int v = (tid < nb) ? bsums[tid] : 0;
    int lane = tid & 31, wid = tid >> 5;
    int inc = v;
    #pragma unroll
    for (int o = 1; o < 32; o <<= 1) {
        int t = __shfl_up_sync(0xffffffffu, inc, o);
        if (lane >= o) inc += t;
    }
    if (lane == 31) wsum[wid] = inc;
    __syncthreads();
    if (tid == 0) {
        int run = 0;
        #pragma unroll
        for (int i = 0; i < 4; i++) { int t = wsum[i]; wsum[i] = run; run += t; }
    }
    __syncthreads();
    if (tid < nb) bsums[tid] = wsum[wid] + inc - v;
}
__global__ void k_scan3(int* __restrict__ rowptr, const int* __restrict__ bsums,
                        int* __restrict__ fill, int n, int E) {
    int i = blockIdx.x * 1024 + threadIdx.x;
    if (i < n) { rowptr[i] += bsums[blockIdx.x]; fill[i] = 0; }
    if (i == 0) rowptr[n] = E;
}
__global__ void k_scatter(const int* __restrict__ srcp, const int* __restrict__ dstp,
                          int E, const int* __restrict__ rowptr, int* __restrict__ fill,
                          const float* __restrict__ dinv,
                          unsigned long long* __restrict__ edge) {
    int e = blockIdx.x * blockDim.x + threadIdx.x;
    if (e >= E) return;
    int s = srcp[e];
    int d = dstp[e];
    int pos = rowptr[d] + atomicAdd(&fill[d], 1);
    unsigned long long w = (unsigned long long)__float_as_uint(dinv[s]);
    edge[pos] = (w << 32) | (unsigned int)s;
}

// ---------------- weight convert ------------------------------------------------
__global__ void k_cvtW(const float* __restrict__ W1, const float* __restrict__ W2,
                       __half* __restrict__ W1h, __half* __restrict__ W2h) {
    int i = blockIdx.x * blockDim.x + threadIdx.x;
    if (i < DIMF * DIMF) {
        W1h[i] = __float2half(W1[i]);
        W2h[i] = __float2half(W2[i]);
    }
}

// ---------------- HMMA GEMM: Y[nrows,128] = X[nrows,128] @ W[128,128] -----------
__device__ __forceinline__ void ldrows(__half (*As)[SROW], const float* X,
                                       int rowbase, int rows, int tid) {
    for (int i = tid; i < rows * 16; i += 256) {
        int r = i >> 4, c8 = (i & 15) * 8;
        const float4* p = (const float4*)(X + (size_t)(rowbase + r) * DIMF + c8);
        float4 f0 = p[0], f1 = p[1];
        __half2 h0 = __floats2half2_rn(f0.x, f0.y), h1 = __floats2half2_rn(f0.z, f0.w);
        __half2 h2 = __floats2half2_rn(f1.x, f1.y), h3 = __floats2half2_rn(f1.z, f1.w);
        uint4 u;
        u.x = *(unsigned*)&h0; u.y = *(unsigned*)&h1;
        u.z = *(unsigned*)&h2; u.w = *(unsigned*)&h3;
        *(uint4*)&As[r][c8] = u;
    }
}
__device__ __forceinline__ void ldrows(__half (*As)[SROW], const __half* X,
                                       int rowbase, int rows, int tid) {
    for (int i = tid; i < rows * 16; i += 256) {
        int r = i >> 4, c8 = (i & 15) * 8;
        *(uint4*)&As[r][c8] = *(const uint4*)(X + (size_t)(rowbase + r) * DIMF + c8);
    }
}

template <typename TIN>
__global__ void k_gemm_hmma(const TIN* __restrict__ X, const __half* __restrict__ Wh,
                            __half* __restrict__ Y, int nrows) {
    extern __shared__ __half smemh[];
    __half (*As)[SROW] = (__half(*)[SROW])smemh;
    __half (*Bs)[SROW] = (__half(*)[SROW])(smemh + 128 * SROW);

    int tid = threadIdx.x;
    int rowbase = blockIdx.x * 128;
    int rows = nrows - rowbase; if (rows > 128) rows = 128;

    #pragma unroll 4
    for (int i = tid; i < 128 * 16; i += 256) {
        int r = i >> 4, c8 = (i & 15) * 8;
        *(uint4*)&Bs[r][c8] = *(const uint4*)(Wh + r * DIMF + c8);
    }
    ldrows(As, X, rowbase, rows, tid);
    __syncthreads();

    int warp = tid >> 5, lane = tid & 31;
    int m0 = warp * 16;
    float acc[16][4];
    #pragma unroll
    for (int i = 0; i < 16; i++)
        #pragma unroll
        for (int j = 0; j < 4; j++) acc[i][j] = 0.f;

    unsigned a_addr = su32(&As[m0 + (lane & 15)][(lane >> 4) * 8]);
    unsigned b_addr = su32(&Bs[lane & 15][(lane >> 4) * 8]);

    #pragma unroll
    for (int ks = 0; ks < 8; ks++) {
        unsigned a0, a1, a2, a3;
        ldsm4(a0, a1, a2, a3, a_addr + ks * 16 * 2);
        #pragma unroll
        for (int pr = 0; pr < 8; pr++) {
            unsigned b0, b1, b2, b3;
            ldsm4t(b0, b1, b2, b3, b_addr + ks * 16 * (SROW * 2) + pr * 16 * 2);
            mma16816(acc[2 * pr + 0], a0, a1, a2, a3, b0, b1);
            mma16816(acc[2 * pr + 1], a0, a1, a2, a3, b2, b3);
        }
    }

    int orow = lane >> 2, ocol = (lane & 3) * 2;
    int r0 = m0 + orow, r1 = r0 + 8;
    bool g0 = (r0 < rows), g1 = (r1 < rows);
    #pragma unroll
    for (int nb = 0; nb < 16; nb++) {
        if (g0) {
            __half2 v = __floats2half2_rn(acc[nb][0], acc[nb][1]);
            *(__half2*)(Y + (size_t)(rowbase + r0) * DIMF + nb * 8 + ocol) = v;
        }
        if (g1) {
            __half2 v = __floats2half2_rn(acc[nb][2], acc[nb][3]);
            *(__half2*)(Y + (size_t)(rowbase + r1) * DIMF + nb * 8 + ocol) = v;
        }
    }
}

// ---------------- agg core: half-warp edge pairing, 16-edge batches ------------
__device__ __forceinline__ void agg_pair(const uint4 q, const float w, float acc[8]) {
    float2 a0 = __half22float2(*(__half2*)&q.x);
    float2 a1 = __half22float2(*(__half2*)&q.y);
    float2 a2 = __half22float2(*(__half2*)&q.z);
    float2 a3 = __half22float2(*(__half2*)&q.w);
    acc[0] = fmaf(w, a0.x, acc[0]); acc[1] = fmaf(w, a0.y, acc[1]);
    acc[2] = fmaf(w, a1.x, acc[2]); acc[3] = fmaf(w, a1.y, acc[3]);
    acc[4] = fmaf(w, a2.x, acc[4]); acc[5] = fmaf(w, a2.y, acc[5]);
    acc[6] = fmaf(w, a3.x, acc[6]); acc[7] = fmaf(w, a3.y, acc[7]);
}

__device__ __forceinline__ void agg_row(const __half* __restrict__ h16,
                                        const unsigned long long* __restrict__ edge,
                                        const float* __restrict__ dinv,
                                        const float* __restrict__ bias,
                                        int v, int e0, int e1, int lane,
                                        float acc[8]) {
    const uint4* h4 = (const uint4*)h16;   // 16 uint4 per 128-dim fp16 row
    int ep = lane >> 4, cl = lane & 15;
    #pragma unroll
    for (int i = 0; i < 8; i++) acc[i] = 0.f;

    int e = e0;
    for (; e + 16 <= e1; e += 16) {
        unsigned long long p[8];
        uint4 q[8];
        #pragma unroll
        for (int j = 0; j < 8; j++) p[j] = __ldg(edge + e + 2 * j + ep);
        #pragma unroll
        for (int j = 0; j < 8; j++)
            q[j] = __ldg(h4 + (size_t)(unsigned)p[j] * 16 + cl);
        #pragma unroll
        for (int j = 0; j < 8; j++)
            agg_pair(q[j], __uint_as_float((unsigned)(p[j] >> 32)), acc);
    }
    for (; e + 2 <= e1; e += 2) {
        unsigned long long p = __ldg(edge + e + ep);
        uint4 q = __ldg(h4 + (size_t)(unsigned)p * 16 + cl);
        agg_pair(q, __uint_as_float((unsigned)(p >> 32)), acc);
    }
    if (e < e1 && ep == 0) {
        unsigned long long p = __ldg(edge + e);
        uint4 q = __ldg(h4 + (size_t)(unsigned)p * 16 + cl);
        agg_pair(q, __uint_as_float((unsigned)(p >> 32)), acc);
    }

    #pragma unroll
    for (int i = 0; i < 8; i++)
        acc[i] += __shfl_xor_sync(0xffffffffu, acc[i], 16);

    float dv = dinv[v];
    float sw = dv * dv;
    uint4 qs = __ldg(h4 + (size_t)v * 16 + cl);
    float2 s0 = __half22float2(*(__half2*)&qs.x);
    float2 s1 = __half22float2(*(__half2*)&qs.y);
    float2 s2 = __half22float2(*(__half2*)&qs.z);
    float2 s3 = __half22float2(*(__half2*)&qs.w);
    float4 b0 = __ldg((const float4*)bias + cl * 2 + 0);
    float4 b1 = __ldg((const float4*)bias + cl * 2 + 1);
    acc[0] = fmaxf(fmaf(dv, acc[0], fmaf(sw, s0.x, b0.x)), 0.f);
    acc[1] = fmaxf(fmaf(dv, acc[1], fmaf(sw, s0.y, b0.y)), 0.f);
    acc[2] = fmaxf(fmaf(dv, acc[2], fmaf(sw, s1.x, b0.z)), 0.f);
    acc[3] = fmaxf(fmaf(dv, acc[3], fmaf(sw, s1.y, b0.w)), 0.f);
    acc[4] = fmaxf(fmaf(dv, acc[4], fmaf(sw, s2.x, b1.x)), 0.f);
    acc[5] = fmaxf(fmaf(dv, acc[5], fmaf(sw, s2.y, b1.y)), 0.f);
    acc[6] = fmaxf(fmaf(dv, acc[6], fmaf(sw, s3.x, b1.z)), 0.f);
    acc[7] = fmaxf(fmaf(dv, acc[7], fmaf(sw, s3.y, b1.w)), 0.f);
}

// layer-1 aggregation: work-stealing warps, fp16 out (GEMM2 input)
__global__ void k_agg(const __half* __restrict__ h16, const int* __restrict__ rowptr,
                      const unsigned long long* __restrict__ edge,
                      const float* __restrict__ dinv, const float* __restrict__ bias,
                      __half* __restrict__ out, int* __restrict__ ctr, int N) {
    int lane = threadIdx.x & 31;
    for (;;) {
        int v;
        if (lane == 0) v = atomicAdd(ctr, 1);
        v = __shfl_sync(0xffffffffu, v, 0);
        if (v >= N) return;
        int e0 = __ldg(rowptr + v), e1 = __ldg(rowptr + v + 1);
        float acc[8];
        agg_row(h16, edge, dinv, bias, v, e0, e1, lane, acc);
        if (lane < 16) {
            __half2 h0 = __floats2half2_rn(acc[0], acc[1]);
            __half2 h1 = __floats2half2_rn(acc[2], acc[3]);
            __half2 h2 = __floats2half2_rn(acc[4], acc[5]);
            __half2 h3 = __floats2half2_rn(acc[6], acc[7]);
            uint4 u;
            u.x = *(unsigned*)&h0; u.y = *(unsigned*)&h1;
            u.z = *(unsigned*)&h2; u.w = *(unsigned*)&h3;
            ((uint4*)(out + (size_t)v * DIMF))[lane] = u;
        }
    }
}

// layer-2 aggregation fused with FC(128->40) + log_softmax, work-stealing
__global__ void k_agg_fc(const __half* __restrict__ h16, const int* __restrict__ rowptr,
                         const unsigned long long* __restrict__ edge,
                         const float* __restrict__ dinv, const float* __restrict__ bias,
                         const float* __restrict__ Wfc, const float* __restrict__ bfc,
                         float* __restrict__ out, int* __restrict__ ctr, int N) {
    __shared__ __align__(16) float sh[8][DIMF];
    int w = threadIdx.x >> 5;
    int lane = threadIdx.x & 31;
    for (;;) {
        int v;
        if (lane == 0) v = atomicAdd(ctr, 1);
        v = __shfl_sync(0xffffffffu, v, 0);
        if (v >= N) return;

        int e0 = __ldg(rowptr + v), e1 = __ldg(rowptr + v + 1);
        float acc[8];
        agg_row(h16, edge, dinv, bias, v, e0, e1, lane, acc);
        if (lane < 16) {
            int cl = lane;
            ((float4*)&sh[w][0])[cl * 2 + 0] = make_float4(acc[0], acc[1], acc[2], acc[3]);
            ((float4*)&sh[w][0])[cl * 2 + 1] = make_float4(acc[4], acc[5], acc[6], acc[7]);
        }
        __syncwarp();

        float acc0 = 0.f, acc1 = 0.f;
        bool hi = (lane < 8);
        #pragma unroll 4
        for (int k4 = 0; k4 < 32; k4++) {
            float4 xv = ((const float4*)&sh[w][0])[k4];
            int k = k4 * 4;
            acc0 = fmaf(xv.x, __ldg(Wfc + (k + 0) * 40 + lane), acc0);
            acc0 = fmaf(xv.y, __ldg(Wfc + (k + 1) * 40 + lane), acc0);
            acc0 = fmaf(xv.z, __ldg(Wfc + (k + 2) * 40 + lane), acc0);
            acc0 = fmaf(xv.w, __ldg(Wfc + (k + 3) * 40 + lane), acc0);
            if (hi) {
                acc1 = fmaf(xv.x, __ldg(Wfc + (k + 0) * 40 + 32 + lane), acc1);
                acc1 = fmaf(xv.y, __ldg(Wfc + (k + 1) * 40 + 32 + lane), acc1);
                acc1 = fmaf(xv.z, __ldg(Wfc + (k + 2) * 40 + 32 + lane), acc1);
                acc1 = fmaf(xv.w, __ldg(Wfc + (k + 3) * 40 + 32 + lane), acc1);
            }
        }
        acc0 += __ldg(bfc + lane);
        if (hi) acc1 += __ldg(bfc + 32 + lane);

        float m = hi ? fmaxf(acc0, acc1) : acc0;
        #pragma unroll
        for (int o2 = 16; o2; o2 >>= 1) m = fmaxf(m, __shfl_xor_sync(0xffffffffu, m, o2));
        float s = expf(acc0 - m) + (hi ? expf(acc1 - m) : 0.f);
        #pragma unroll
        for (int o2 = 16; o2; o2 >>= 1) s += __shfl_xor_sync(0xffffffffu, s, o2);
        float lse = logf(s) + m;

        out[(size_t)v * 40 + lane] = acc0 - lse;
        if (hi) out[(size_t)v * 40 + 32 + lane] = acc1 - lse;
        __syncwarp();
    }
}

// ---------------- host launcher ----------------------------------------------
extern "C" void kernel_launch(void* const* d_in, const int* in_sizes, int n_in,
                              void* d_out, int out_size) {
    const float* x    = (const float*)d_in[0];
    const float* W1   = (const float*)d_in[1];
    const float* b1   = (const float*)d_in[2];
    const float* W2   = (const float*)d_in[3];
    const float* b2   = (const float*)d_in[4];
    const float* Wfc  = (const float*)d_in[5];
    const float* bfc  = (const float*)d_in[6];
    const int*   eidx = (const int*)d_in[7];
    float* out = (float*)d_out;

    int N = in_sizes[0] / DIMF;
    int E = in_sizes[7] / 2;
    if (N > NMAX) N = NMAX;
    if (E > EMAX) E = EMAX;

    __half *ph16, *pb16, *pW1h, *pW2h;
    float* pdinv;
    int *pdeg, *prow, *pbs, *pctr;
    unsigned long long* pedge;
    cudaGetSymbolAddress((void**)&ph16,  g_h16);
    cudaGetSymbolAddress((void**)&pb16,  g_b16);
    cudaGetSymbolAddress((void**)&pW1h,  g_W1h);
    cudaGetSymbolAddress((void**)&pW2h,  g_W2h);
    cudaGetSymbolAddress((void**)&pdeg,  g_deg);
    cudaGetSymbolAddress((void**)&pdinv, g_dinv);
    cudaGetSymbolAddress((void**)&prow,  g_rowptr);
    cudaGetSymbolAddress((void**)&pbs,   g_bsums);
    cudaGetSymbolAddress((void**)&pctr,  g_ctr);
    cudaGetSymbolAddress((void**)&pedge, g_edge);

    int smem_gemm = 2 * 128 * SROW * (int)sizeof(__half);   // 69632 B
    cudaFuncSetAttribute(k_gemm_hmma<float>,
                         cudaFuncAttributeMaxDynamicSharedMemorySize, smem_gemm);
    cudaFuncSetAttribute(k_gemm_hmma<__half>,
                         cudaFuncAttributeMaxDynamicSharedMemorySize, smem_gemm);

    static cudaStream_t s2 = nullptr;
    static cudaEvent_t evFork = nullptr, evJoin = nullptr;
    if (s2 == nullptr) {
        cudaStreamCreateWithFlags(&s2, cudaStreamNonBlocking);
        cudaEventCreateWithFlags(&evFork, cudaEventDisableTiming);
        cudaEventCreateWithFlags(&evJoin, cudaEventDisableTiming);
    }

    const int* srcp = eidx;
    const int* dstp = eidx + E;

    int gb = (N + 127) / 128;
    int nb = (N + 1023) / 1024;
    int agg_blocks = 148 * 4;   // persistent-ish; extra blocks exit on first steal

    // ---- fork: cvtW + GEMM1 on side stream, CSR chain on main stream ----
    cudaEventRecord(evFork, 0);
    cudaStreamWaitEvent(s2, evFork, 0);
    k_cvtW<<<(DIMF * DIMF + 255) / 256, 256, 0, s2>>>(W1, W2, pW1h, pW2h);
    k_gemm_hmma<float><<<gb, 256, smem_gemm, s2>>>(x, pW1h, ph16, N);
    cudaEventRecord(evJoin, s2);

    // main stream: CSR build (+ zero work-steal counters)
    cudaMemsetAsync(pdeg, 0, (size_t)N * sizeof(int));
    cudaMemsetAsync(pctr, 0, 2 * sizeof(int));
    k_hist<<<(E + 255) / 256, 256>>>(dstp, E, pdeg);
    k_scan1<<<nb, 256>>>(pdeg, prow, pbs, pdinv, N);
    k_scan2<<<1, 128>>>(pbs, nb);
    k_scan3<<<nb, 1024>>>(prow, pbs, pdeg, N, E);
    k_scatter<<<(E + 255) / 256, 256>>>(srcp, dstp, E, prow, pdeg, pdinv, pedge);

    // join: agg1 needs GEMM1 output + CSR
    cudaStreamWaitEvent(0, evJoin, 0);
    k_agg<<<agg_blocks, 256>>>(ph16, prow, pedge, pdinv, b1, pb16, pctr, N);

    // layer 2 + fused agg/FC/log_softmax
    k_gemm_hmma<__half><<<gb, 256, smem_gemm>>>(pb16, pW2h, ph16, N);
    k_agg_fc<<<agg_blocks, 256>>>(ph16, prow, pedge, pdinv, b2, Wfc, bfc, out,
                                  pctr + 1, N);
}

// round 15
// speedup vs baseline: 1.1682x; 1.1682x over previous
#include <cuda_runtime.h>
#include <cuda_fp16.h>
#include <math.h>

#define NMAX 100000
#define EMAX 3200000
#define DIMF 128
#define SROW (DIMF + 8)   // padded smem row (halves)

// ---------------- scratch ----------------------------------------------------
__device__ __align__(16) __half g_h16[(size_t)NMAX * DIMF];  // GEMM out (gathered)
__device__ __align__(16) __half g_b16[(size_t)NMAX * DIMF];  // agg1 out (GEMM2 in)
__device__ __align__(16) __half g_W1h[DIMF * DIMF];
__device__ __align__(16) __half g_W2h[DIMF * DIMF];
__device__ __align__(16) int    g_deg[NMAX];
__device__ __align__(16) float  g_dinv[NMAX];
__device__ __align__(16) int    g_rowptr[NMAX + 1];
__device__ __align__(16) int    g_bsums[512];
__device__ __align__(16) unsigned long long g_edge[EMAX];    // {ws_bits:32 | col:32}

// ---------------- mma / ldmatrix helpers --------------------------------------
__device__ __forceinline__ unsigned su32(const void* p) {
    return (unsigned)__cvta_generic_to_shared(p);
}
__device__ __forceinline__ void ldsm4(unsigned& r0, unsigned& r1, unsigned& r2,
                                      unsigned& r3, unsigned addr) {
    asm volatile("ldmatrix.sync.aligned.m8n8.x4.shared.b16 {%0,%1,%2,%3}, [%4];"
                 : "=r"(r0), "=r"(r1), "=r"(r2), "=r"(r3) : "r"(addr));
}
__device__ __forceinline__ void ldsm4t(unsigned& r0, unsigned& r1, unsigned& r2,
                                       unsigned& r3, unsigned addr) {
    asm volatile("ldmatrix.sync.aligned.m8n8.x4.trans.shared.b16 {%0,%1,%2,%3}, [%4];"
                 : "=r"(r0), "=r"(r1), "=r"(r2), "=r"(r3) : "r"(addr));
}
__device__ __forceinline__ void mma16816(float* d, unsigned a0, unsigned a1,
                                         unsigned a2, unsigned a3,
                                         unsigned b0, unsigned b1) {
    asm volatile("mma.sync.aligned.m16n8k16.row.col.f32.f16.f16.f32 "
                 "{%0,%1,%2,%3},{%4,%5,%6,%7},{%8,%9},{%0,%1,%2,%3};"
                 : "+f"(d[0]), "+f"(d[1]), "+f"(d[2]), "+f"(d[3])
                 : "r"(a0), "r"(a1), "r"(a2), "r"(a3), "r"(b0), "r"(b1));
}

// ---------------- CSR build ----------------------------------------------------
__global__ void k_hist(const int* __restrict__ dst, int E, int* __restrict__ deg) {
    int e = blockIdx.x * blockDim.x + threadIdx.x;
    if (e < E) atomicAdd(&deg[dst[e]], 1);
}
__global__ void k_scan1(const int* __restrict__ in, int* __restrict__ out,
                        int* __restrict__ bsums, float* __restrict__ dinv, int n) {
    __shared__ int wsum[8];
    int tid  = threadIdx.x;
    int base = blockIdx.x * 1024 + tid * 4;
    int v0 = 0, v1 = 0, v2 = 0, v3 = 0;
    if (base + 0 < n) v0 = in[base + 0];
    if (base + 1 < n) v1 = in[base + 1];
    if (base + 2 < n) v2 = in[base + 2];
    if (base + 3 < n) v3 = in[base + 3];
    if (base + 0 < n) dinv[base + 0] = rsqrtf((float)(v0 + 1));
    if (base + 1 < n) dinv[base + 1] = rsqrtf((float)(v1 + 1));
    if (base + 2 < n) dinv[base + 2] = rsqrtf((float)(v2 + 1));
    if (base + 3 < n) dinv[base + 3] = rsqrtf((float)(v3 + 1));
    int s = v0 + v1 + v2 + v3;
    int lane = tid & 31, wid = tid >> 5;
    int inc = s;
    #pragma unroll
    for (int o = 1; o < 32; o <<= 1) {
        int t = __shfl_up_sync(0xffffffffu, inc, o);
        if (lane >= o) inc += t;
    }
    if (lane == 31) wsum[wid] = inc;
    __syncthreads();
    if (tid == 0) {
        int run = 0;
        #pragma unroll
        for (int i = 0; i < 8; i++) { int t = wsum[i]; wsum[i] = run; run += t; }
        bsums[blockIdx.x] = run;
    }
    __syncthreads();
    int ex = wsum[wid] + inc - s;
    if (base + 0 < n) out[base + 0] = ex;
    if (base + 1 < n) out[base + 1] = ex + v0;
    if (base + 2 < n) out[base + 2] = ex + v0 + v1;
    if (base + 3 < n) out[base + 3] = ex + v0 + v1 + v2;
}
__global__ void k_scan2(int* __restrict__ bsums, int nb) {
    __shared__ int wsum[4];
    int tid = threadIdx.x;
    int v = (tid < nb) ? bsums[tid] : 0;
    int lane = tid & 31, wid = tid >> 5;
    int inc = v;
    #pragma unroll
    for (int o = 1; o < 32; o <<= 1) {
        int t = __shfl_up_sync(0xffffffffu, inc, o);
        if (lane >= o) inc += t;
    }
    if (lane == 31) wsum[wid] = inc;
    __syncthreads();
    if (tid == 0) {
        int run = 0;
        #pragma unroll
        for (int i = 0; i < 4; i++) { int t = wsum[i]; wsum[i] = run; run += t; }
    }
    __syncthreads();
    if (tid < nb) bsums[tid] = wsum[wid] + inc - v;
}
__global__ void k_scan3(int* __restrict__ rowptr, const int* __restrict__ bsums,
                        int* __restrict__ fill, int n, int E) {
    int i = blockIdx.x * 1024 + threadIdx.x;
    if (i < n) { rowptr[i] += bsums[blockIdx.x]; fill[i] = 0; }
    if (i == 0) rowptr[n] = E;
}
__global__ void k_scatter(const int* __restrict__ srcp, const int* __restrict__ dstp,
                          int E, const int* __restrict__ rowptr, int* __restrict__ fill,
                          const float* __restrict__ dinv,
                          unsigned long long* __restrict__ edge) {
    int e = blockIdx.x * blockDim.x + threadIdx.x;
    if (e >= E) return;
    int s = srcp[e];
    int d = dstp[e];
    int pos = rowptr[d] + atomicAdd(&fill[d], 1);
    unsigned long long w = (unsigned long long)__float_as_uint(dinv[s]);
    edge[pos] = (w << 32) | (unsigned int)s;
}

// ---------------- weight convert ------------------------------------------------
__global__ void k_cvtW(const float* __restrict__ W1, const float* __restrict__ W2,
                       __half* __restrict__ W1h, __half* __restrict__ W2h) {
    int i = blockIdx.x * blockDim.x + threadIdx.x;
    if (i < DIMF * DIMF) {
        W1h[i] = __float2half(W1[i]);
        W2h[i] = __float2half(W2[i]);
    }
}

// ---------------- HMMA GEMM: Y[nrows,128] = X[nrows,128] @ W[128,128] -----------
__device__ __forceinline__ void ldrows(__half (*As)[SROW], const float* X,
                                       int rowbase, int rows, int tid) {
    for (int i = tid; i < rows * 16; i += 256) {
        int r = i >> 4, c8 = (i & 15) * 8;
        const float4* p = (const float4*)(X + (size_t)(rowbase + r) * DIMF + c8);
        float4 f0 = p[0], f1 = p[1];
        __half2 h0 = __floats2half2_rn(f0.x, f0.y), h1 = __floats2half2_rn(f0.z, f0.w);
        __half2 h2 = __floats2half2_rn(f1.x, f1.y), h3 = __floats2half2_rn(f1.z, f1.w);
        uint4 u;
        u.x = *(unsigned*)&h0; u.y = *(unsigned*)&h1;
        u.z = *(unsigned*)&h2; u.w = *(unsigned*)&h3;
        *(uint4*)&As[r][c8] = u;
    }
}
__device__ __forceinline__ void ldrows(__half (*As)[SROW], const __half* X,
                                       int rowbase, int rows, int tid) {
    for (int i = tid; i < rows * 16; i += 256) {
        int r = i >> 4, c8 = (i & 15) * 8;
        *(uint4*)&As[r][c8] = *(const uint4*)(X + (size_t)(rowbase + r) * DIMF + c8);
    }
}

template <typename TIN>
__global__ void k_gemm_hmma(const TIN* __restrict__ X, const __half* __restrict__ Wh,
                            __half* __restrict__ Y, int nrows) {
    extern __shared__ __half smemh[];
    __half (*As)[SROW] = (__half(*)[SROW])smemh;
    __half (*Bs)[SROW] = (__half(*)[SROW])(smemh + 128 * SROW);

    int tid = threadIdx.x;
    int rowbase = blockIdx.x * 128;
    int rows = nrows - rowbase; if (rows > 128) rows = 128;

    #pragma unroll 4
    for (int i = tid; i < 128 * 16; i += 256) {
        int r = i >> 4, c8 = (i & 15) * 8;
        *(uint4*)&Bs[r][c8] = *(const uint4*)(Wh + r * DIMF + c8);
    }
    ldrows(As, X, rowbase, rows, tid);
    __syncthreads();

    int warp = tid >> 5, lane = tid & 31;
    int m0 = warp * 16;
    float acc[16][4];
    #pragma unroll
    for (int i = 0; i < 16; i++)
        #pragma unroll
        for (int j = 0; j < 4; j++) acc[i][j] = 0.f;

    unsigned a_addr = su32(&As[m0 + (lane & 15)][(lane >> 4) * 8]);
    unsigned b_addr = su32(&Bs[lane & 15][(lane >> 4) * 8]);

    #pragma unroll
    for (int ks = 0; ks < 8; ks++) {
        unsigned a0, a1, a2, a3;
        ldsm4(a0, a1, a2, a3, a_addr + ks * 16 * 2);
        #pragma unroll
        for (int pr = 0; pr < 8; pr++) {
            unsigned b0, b1, b2, b3;
            ldsm4t(b0, b1, b2, b3, b_addr + ks * 16 * (SROW * 2) + pr * 16 * 2);
            mma16816(acc[2 * pr + 0], a0, a1, a2, a3, b0, b1);
            mma16816(acc[2 * pr + 1], a0, a1, a2, a3, b2, b3);
        }
    }

    int orow = lane >> 2, ocol = (lane & 3) * 2;
    int r0 = m0 + orow, r1 = r0 + 8;
    bool g0 = (r0 < rows), g1 = (r1 < rows);
    #pragma unroll
    for (int nb = 0; nb < 16; nb++) {
        if (g0) {
            __half2 v = __floats2half2_rn(acc[nb][0], acc[nb][1]);
            *(__half2*)(Y + (size_t)(rowbase + r0) * DIMF + nb * 8 + ocol) = v;
        }
        if (g1) {
            __half2 v = __floats2half2_rn(acc[nb][2], acc[nb][3]);
            *(__half2*)(Y + (size_t)(rowbase + r1) * DIMF + nb * 8 + ocol) = v;
        }
    }
}

// ---------------- agg core: half-warp edge pairing, 8-edge batches -------------
// ep = lane>>4 (edge parity), cl = lane&15 (8-dim chunk). 4 outstanding LDG.128
// per lane, low register footprint (fits 64 regs -> 4 blocks/SM = 32 warps/SM).
__device__ __forceinline__ void agg_pair(const uint4 q, const float w, float acc[8]) {
    float2 a0 = __half22float2(*(__half2*)&q.x);
    float2 a1 = __half22float2(*(__half2*)&q.y);
    float2 a2 = __half22float2(*(__half2*)&q.z);
    float2 a3 = __half22float2(*(__half2*)&q.w);
    acc[0] = fmaf(w, a0.x, acc[0]); acc[1] = fmaf(w, a0.y, acc[1]);
    acc[2] = fmaf(w, a1.x, acc[2]); acc[3] = fmaf(w, a1.y, acc[3]);
    acc[4] = fmaf(w, a2.x, acc[4]); acc[5] = fmaf(w, a2.y, acc[5]);
    acc[6] = fmaf(w, a3.x, acc[6]); acc[7] = fmaf(w, a3.y, acc[7]);
}

__device__ __forceinline__ void agg_row(const __half* __restrict__ h16,
                                        const unsigned long long* __restrict__ edge,
                                        const float* __restrict__ dinv,
                                        const float* __restrict__ bias,
                                        int v, int e0, int e1, int lane,
                                        float acc[8]) {
    const uint4* h4 = (const uint4*)h16;   // 16 uint4 per 128-dim fp16 row
    int ep = lane >> 4, cl = lane & 15;
    #pragma unroll
    for (int i = 0; i < 8; i++) acc[i] = 0.f;

    int e = e0;
    // 4 pairs = 8 edges per batch; 4 outstanding LDG.128 per lane
    for (; e + 8 <= e1; e += 8) {
        unsigned long long p[4];
        uint4 q[4];
        #pragma unroll
        for (int j = 0; j < 4; j++) p[j] = __ldg(edge + e + 2 * j + ep);
        #pragma unroll
        for (int j = 0; j < 4; j++)
            q[j] = __ldg(h4 + (size_t)(unsigned)p[j] * 16 + cl);
        #pragma unroll
        for (int j = 0; j < 4; j++)
            agg_pair(q[j], __uint_as_float((unsigned)(p[j] >> 32)), acc);
    }
    // pair tail
    for (; e + 2 <= e1; e += 2) {
        unsigned long long p = __ldg(edge + e + ep);
        uint4 q = __ldg(h4 + (size_t)(unsigned)p * 16 + cl);
        agg_pair(q, __uint_as_float((unsigned)(p >> 32)), acc);
    }
    // single leftover edge: ep==0 half only
    if (e < e1 && ep == 0) {
        unsigned long long p = __ldg(edge + e);
        uint4 q = __ldg(h4 + (size_t)(unsigned)p * 16 + cl);
        agg_pair(q, __uint_as_float((unsigned)(p >> 32)), acc);
    }

    // merge edge-parity halves
    #pragma unroll
    for (int i = 0; i < 8; i++)
        acc[i] += __shfl_xor_sync(0xffffffffu, acc[i], 16);

    // self-loop + bias + relu
    float dv = dinv[v];
    float sw = dv * dv;
    uint4 qs = __ldg(h4 + (size_t)v * 16 + cl);
    float2 s0 = __half22float2(*(__half2*)&qs.x);
    float2 s1 = __half22float2(*(__half2*)&qs.y);
    float2 s2 = __half22float2(*(__half2*)&qs.z);
    float2 s3 = __half22float2(*(__half2*)&qs.w);
    float4 b0 = __ldg((const float4*)bias + cl * 2 + 0);
    float4 b1 = __ldg((const float4*)bias + cl * 2 + 1);
    acc[0] = fmaxf(fmaf(dv, acc[0], fmaf(sw, s0.x, b0.x)), 0.f);
    acc[1] = fmaxf(fmaf(dv, acc[1], fmaf(sw, s0.y, b0.y)), 0.f);
    acc[2] = fmaxf(fmaf(dv, acc[2], fmaf(sw, s1.x, b0.z)), 0.f);
    acc[3] = fmaxf(fmaf(dv, acc[3], fmaf(sw, s1.y, b0.w)), 0.f);
    acc[4] = fmaxf(fmaf(dv, acc[4], fmaf(sw, s2.x, b1.x)), 0.f);
    acc[5] = fmaxf(fmaf(dv, acc[5], fmaf(sw, s2.y, b1.y)), 0.f);
    acc[6] = fmaxf(fmaf(dv, acc[6], fmaf(sw, s3.x, b1.z)), 0.f);
    acc[7] = fmaxf(fmaf(dv, acc[7], fmaf(sw, s3.y, b1.w)), 0.f);
}

// layer-1 aggregation: fp16 out (GEMM2 input); regs pinned for 4 blocks/SM
__global__ void __launch_bounds__(256, 4)
k_agg(const __half* __restrict__ h16, const int* __restrict__ rowptr,
      const unsigned long long* __restrict__ edge,
      const float* __restrict__ dinv, const float* __restrict__ bias,
      __half* __restrict__ out, int N) {
    int v = (blockIdx.x * blockDim.x + threadIdx.x) >> 5;
    int lane = threadIdx.x & 31;
    if (v >= N) return;
    int e0 = __ldg(rowptr + v), e1 = __ldg(rowptr + v + 1);
    float acc[8];
    agg_row(h16, edge, dinv, bias, v, e0, e1, lane, acc);
    if (lane < 16) {
        __half2 h0 = __floats2half2_rn(acc[0], acc[1]);
        __half2 h1 = __floats2half2_rn(acc[2], acc[3]);
        __half2 h2 = __floats2half2_rn(acc[4], acc[5]);
        __half2 h3 = __floats2half2_rn(acc[6], acc[7]);
        uint4 u;
        u.x = *(unsigned*)&h0; u.y = *(unsigned*)&h1;
        u.z = *(unsigned*)&h2; u.w = *(unsigned*)&h3;
        ((uint4*)(out + (size_t)v * DIMF))[lane] = u;
    }
}

// layer-2 aggregation fused with FC(128->40) + log_softmax
__global__ void __launch_bounds__(256, 4)
k_agg_fc(const __half* __restrict__ h16, const int* __restrict__ rowptr,
         const unsigned long long* __restrict__ edge,
         const float* __restrict__ dinv, const float* __restrict__ bias,
         const float* __restrict__ Wfc, const float* __restrict__ bfc,
         float* __restrict__ out, int N) {
    __shared__ __align__(16) float sh[8][DIMF];
    int w = threadIdx.x >> 5;
    int lane = threadIdx.x & 31;
    int v = blockIdx.x * 8 + w;
    if (v >= N) return;

    int e0 = __ldg(rowptr + v), e1 = __ldg(rowptr + v + 1);
    float acc[8];
    agg_row(h16, edge, dinv, bias, v, e0, e1, lane, acc);
    if (lane < 16) {
        int cl = lane;
        ((float4*)&sh[w][0])[cl * 2 + 0] = make_float4(acc[0], acc[1], acc[2], acc[3]);
        ((float4*)&sh[w][0])[cl * 2 + 1] = make_float4(acc[4], acc[5], acc[6], acc[7]);
    }
    __syncwarp();

    float acc0 = 0.f, acc1 = 0.f;
    bool hi = (lane < 8);
    #pragma unroll 4
    for (int k4 = 0; k4 < 32; k4++) {
        float4 xv = ((const float4*)&sh[w][0])[k4];
        int k = k4 * 4;
        acc0 = fmaf(xv.x, __ldg(Wfc + (k + 0) * 40 + lane), acc0);
        acc0 = fmaf(xv.y, __ldg(Wfc + (k + 1) * 40 + lane), acc0);
        acc0 = fmaf(xv.z, __ldg(Wfc + (k + 2) * 40 + lane), acc0);
        acc0 = fmaf(xv.w, __ldg(Wfc + (k + 3) * 40 + lane), acc0);
        if (hi) {
            acc1 = fmaf(xv.x, __ldg(Wfc + (k + 0) * 40 + 32 + lane), acc1);
            acc1 = fmaf(xv.y, __ldg(Wfc + (k + 1) * 40 + 32 + lane), acc1);
            acc1 = fmaf(xv.z, __ldg(Wfc + (k + 2) * 40 + 32 + lane), acc1);
            acc1 = fmaf(xv.w, __ldg(Wfc + (k + 3) * 40 + 32 + lane), acc1);
        }
    }
    acc0 += __ldg(bfc + lane);
    if (hi) acc1 += __ldg(bfc + 32 + lane);

    float m = hi ? fmaxf(acc0, acc1) : acc0;
    #pragma unroll
    for (int o2 = 16; o2; o2 >>= 1) m = fmaxf(m, __shfl_xor_sync(0xffffffffu, m, o2));
    float s = expf(acc0 - m) + (hi ? expf(acc1 - m) : 0.f);
    #pragma unroll
    for (int o2 = 16; o2; o2 >>= 1) s += __shfl_xor_sync(0xffffffffu, s, o2);
    float lse = logf(s) + m;

    out[(size_t)v * 40 + lane] = acc0 - lse;
    if (hi) out[(size_t)v * 40 + 32 + lane] = acc1 - lse;
}

// ---------------- host launcher ----------------------------------------------
extern "C" void kernel_launch(void* const* d_in, const int* in_sizes, int n_in,
                              void* d_out, int out_size) {
    const float* x    = (const float*)d_in[0];
    const float* W1   = (const float*)d_in[1];
    const float* b1   = (const float*)d_in[2];
    const float* W2   = (const float*)d_in[3];
    const float* b2   = (const float*)d_in[4];
    const float* Wfc  = (const float*)d_in[5];
    const float* bfc  = (const float*)d_in[6];
    const int*   eidx = (const int*)d_in[7];
    float* out = (float*)d_out;

    int N = in_sizes[0] / DIMF;
    int E = in_sizes[7] / 2;
    if (N > NMAX) N = NMAX;
    if (E > EMAX) E = EMAX;

    __half *ph16, *pb16, *pW1h, *pW2h;
    float* pdinv;
    int *pdeg, *prow, *pbs;
    unsigned long long* pedge;
    cudaGetSymbolAddress((void**)&ph16,  g_h16);
    cudaGetSymbolAddress((void**)&pb16,  g_b16);
    cudaGetSymbolAddress((void**)&pW1h,  g_W1h);
    cudaGetSymbolAddress((void**)&pW2h,  g_W2h);
    cudaGetSymbolAddress((void**)&pdeg,  g_deg);
    cudaGetSymbolAddress((void**)&pdinv, g_dinv);
    cudaGetSymbolAddress((void**)&prow,  g_rowptr);
    cudaGetSymbolAddress((void**)&pbs,   g_bsums);
    cudaGetSymbolAddress((void**)&pedge, g_edge);

    int smem_gemm = 2 * 128 * SROW * (int)sizeof(__half);   // 69632 B
    cudaFuncSetAttribute(k_gemm_hmma<float>,
                         cudaFuncAttributeMaxDynamicSharedMemorySize, smem_gemm);
    cudaFuncSetAttribute(k_gemm_hmma<__half>,
                         cudaFuncAttributeMaxDynamicSharedMemorySize, smem_gemm);

    static cudaStream_t s2 = nullptr;
    static cudaEvent_t evFork = nullptr, evJoin = nullptr;
    if (s2 == nullptr) {
        cudaStreamCreateWithFlags(&s2, cudaStreamNonBlocking);
        cudaEventCreateWithFlags(&evFork, cudaEventDisableTiming);
        cudaEventCreateWithFlags(&evJoin, cudaEventDisableTiming);
    }

    const int* srcp = eidx;
    const int* dstp = eidx + E;

    int gb = (N + 127) / 128;
    int ab = (N * 32 + 255) / 256;
    int nb = (N + 1023) / 1024;

    // ---- fork: cvtW + GEMM1 on side stream, CSR chain on main stream ----
    cudaEventRecord(evFork, 0);
    cudaStreamWaitEvent(s2, evFork, 0);
    k_cvtW<<<(DIMF * DIMF + 255) / 256, 256, 0, s2>>>(W1, W2, pW1h, pW2h);
    k_gemm_hmma<float><<<gb, 256, smem_gemm, s2>>>(x, pW1h, ph16, N);
    cudaEventRecord(evJoin, s2);

    // main stream: CSR build
    cudaMemsetAsync(pdeg, 0, (size_t)N * sizeof(int));
    k_hist<<<(E + 255) / 256, 256>>>(dstp, E, pdeg);
    k_scan1<<<nb, 256>>>(pdeg, prow, pbs, pdinv, N);
    k_scan2<<<1, 128>>>(pbs, nb);
    k_scan3<<<nb, 1024>>>(prow, pbs, pdeg, N, E);
    k_scatter<<<(E + 255) / 256, 256>>>(srcp, dstp, E, prow, pdeg, pdinv, pedge);

    // join: agg1 needs GEMM1 output + CSR
    cudaStreamWaitEvent(0, evJoin, 0);
    k_agg<<<ab, 256>>>(ph16, prow, pedge, pdinv, b1, pb16, N);

    // layer 2 + fused agg/FC/log_softmax
    k_gemm_hmma<__half><<<gb, 256, smem_gemm>>>(pb16, pW2h, ph16, N);
    k_agg_fc<<<(N + 7) / 8, 256>>>(ph16, prow, pedge, pdinv, b2, Wfc, bfc, out, N);
}

// round 16
// speedup vs baseline: 1.1723x; 1.0035x over previous
#include <cuda_runtime.h>
#include <cuda_fp16.h>
#include <math.h>

#define NMAX 100000
#define EMAX 3200000
#define DIMF 128
#define SROW (DIMF + 8)   // padded smem row (halves)

// ---------------- scratch ----------------------------------------------------
__device__ __align__(16) __half g_h16[(size_t)NMAX * DIMF];  // GEMM out (gathered)
__device__ __align__(16) __half g_b16[(size_t)NMAX * DIMF];  // agg1 out (GEMM2 in)
__device__ __align__(16) int    g_deg[NMAX];
__device__ __align__(16) float  g_dinv[NMAX];
__device__ __align__(16) int    g_rowptr[NMAX + 1];
__device__ __align__(16) int    g_bsums[512];
__device__ __align__(16) unsigned long long g_edge[EMAX];    // {ws_bits:32 | col:32}

// ---------------- mma / ldmatrix helpers --------------------------------------
__device__ __forceinline__ unsigned su32(const void* p) {
    return (unsigned)__cvta_generic_to_shared(p);
}
__device__ __forceinline__ void ldsm4(unsigned& r0, unsigned& r1, unsigned& r2,
                                      unsigned& r3, unsigned addr) {
    asm volatile("ldmatrix.sync.aligned.m8n8.x4.shared.b16 {%0,%1,%2,%3}, [%4];"
                 : "=r"(r0), "=r"(r1), "=r"(r2), "=r"(r3) : "r"(addr));
}
__device__ __forceinline__ void ldsm4t(unsigned& r0, unsigned& r1, unsigned& r2,
                                       unsigned& r3, unsigned addr) {
    asm volatile("ldmatrix.sync.aligned.m8n8.x4.trans.shared.b16 {%0,%1,%2,%3}, [%4];"
                 : "=r"(r0), "=r"(r1), "=r"(r2), "=r"(r3) : "r"(addr));
}
__device__ __forceinline__ void mma16816(float* d, unsigned a0, unsigned a1,
                                         unsigned a2, unsigned a3,
                                         unsigned b0, unsigned b1) {
    asm volatile("mma.sync.aligned.m16n8k16.row.col.f32.f16.f16.f32 "
                 "{%0,%1,%2,%3},{%4,%5,%6,%7},{%8,%9},{%0,%1,%2,%3};"
                 : "+f"(d[0]), "+f"(d[1]), "+f"(d[2]), "+f"(d[3])
                 : "r"(a0), "r"(a1), "r"(a2), "r"(a3), "r"(b0), "r"(b1));
}

// ---------------- CSR build ----------------------------------------------------
__global__ void k_hist(const int* __restrict__ dst, int E, int* __restrict__ deg) {
    int e = blockIdx.x * blockDim.x + threadIdx.x;
    if (e < E) atomicAdd(&deg[dst[e]], 1);
}
__global__ void k_scan1(const int* __restrict__ in, int* __restrict__ out,
                        int* __restrict__ bsums, float* __restrict__ dinv, int n) {
    __shared__ int wsum[8];
    int tid  = threadIdx.x;
    int base = blockIdx.x * 1024 + tid * 4;
    int v0 = 0, v1 = 0, v2 = 0, v3 = 0;
    if (base + 0 < n) v0 = in[base + 0];
    if (base + 1 < n) v1 = in[base + 1];
    if (base + 2 < n) v2 = in[base + 2];
    if (base + 3 < n) v3 = in[base + 3];
    if (base + 0 < n) dinv[base + 0] = rsqrtf((float)(v0 + 1));
    if (base + 1 < n) dinv[base + 1] = rsqrtf((float)(v1 + 1));
    if (base + 2 < n) dinv[base + 2] = rsqrtf((float)(v2 + 1));
    if (base + 3 < n) dinv[base + 3] = rsqrtf((float)(v3 + 1));
    int s = v0 + v1 + v2 + v3;
    int lane = tid & 31, wid = tid >> 5;
    int inc = s;
    #pragma unroll
    for (int o = 1; o < 32; o <<= 1) {
        int t = __shfl_up_sync(0xffffffffu, inc, o);
        if (lane >= o) inc += t;
    }
    if (lane == 31) wsum[wid] = inc;
    __syncthreads();
    if (tid == 0) {
        int run = 0;
        #pragma unroll
        for (int i = 0; i < 8; i++) { int t = wsum[i]; wsum[i] = run; run += t; }
        bsums[blockIdx.x] = run;
    }
    __syncthreads();
    int ex = wsum[wid] + inc - s;
    if (base + 0 < n) out[base + 0] = ex;
    if (base + 1 < n) out[base + 1] = ex + v0;
    if (base + 2 < n) out[base + 2] = ex + v0 + v1;
    if (base + 3 < n) out[base + 3] = ex + v0 + v1 + v2;
}
// merged scan2+scan3: each block sums bsums[0..blockIdx-1] in-block (nb<=98<1024),
// adds to its rowptr chunk, zeroes fill counters.
__global__ void k_scan23(int* __restrict__ rowptr, const int* __restrict__ bsums,
                         int* __restrict__ fill, int n, int E) {
    __shared__ int wsum[32];
    int t = threadIdx.x;   // blockDim = 1024
    int b = blockIdx.x;
    int val = (t < b) ? bsums[t] : 0;   // nb <= 98 < 1024
    int lane = t & 31, wid = t >> 5;
    #pragma unroll
    for (int o = 16; o; o >>= 1) val += __shfl_xor_sync(0xffffffffu, val, o);
    if (lane == 0) wsum[wid] = val;
    __syncthreads();
    if (t == 0) {
        int tot = 0;
        #pragma unroll
        for (int i = 0; i < 32; i++) tot += wsum[i];
        wsum[0] = tot;
    }
    __syncthreads();
    int off = wsum[0];
    int i = b * 1024 + t;
    if (i < n) { rowptr[i] += off; fill[i] = 0; }
    if (i == 0) rowptr[n] = E;
}
__global__ void k_scatter(const int* __restrict__ srcp, const int* __restrict__ dstp,
                          int E, const int* __restrict__ rowptr, int* __restrict__ fill,
                          const float* __restrict__ dinv,
                          unsigned long long* __restrict__ edge) {
    int e = blockIdx.x * blockDim.x + threadIdx.x;
    if (e >= E) return;
    int s = srcp[e];
    int d = dstp[e];
    int pos = rowptr[d] + atomicAdd(&fill[d], 1);
    unsigned long long w = (unsigned long long)__float_as_uint(dinv[s]);
    edge[pos] = (w << 32) | (unsigned int)s;
}

// ---------------- HMMA GEMM: in-block W fp32->fp16, optional deg zeroing -------
__device__ __forceinline__ void ldrows(__half (*As)[SROW], const float* X,
                                       int rowbase, int rows, int tid) {
    for (int i = tid; i < rows * 16; i += 256) {
        int r = i >> 4, c8 = (i & 15) * 8;
        const float4* p = (const float4*)(X + (size_t)(rowbase + r) * DIMF + c8);
        float4 f0 = p[0], f1 = p[1];
        __half2 h0 = __floats2half2_rn(f0.x, f0.y), h1 = __floats2half2_rn(f0.z, f0.w);
        __half2 h2 = __floats2half2_rn(f1.x, f1.y), h3 = __floats2half2_rn(f1.z, f1.w);
        uint4 u;
        u.x = *(unsigned*)&h0; u.y = *(unsigned*)&h1;
        u.z = *(unsigned*)&h2; u.w = *(unsigned*)&h3;
        *(uint4*)&As[r][c8] = u;
    }
}
__device__ __forceinline__ void ldrows(__half (*As)[SROW], const __half* X,
                                       int rowbase, int rows, int tid) {
    for (int i = tid; i < rows * 16; i += 256) {
        int r = i >> 4, c8 = (i & 15) * 8;
        *(uint4*)&As[r][c8] = *(const uint4*)(X + (size_t)(rowbase + r) * DIMF + c8);
    }
}

template <typename TIN>
__global__ void k_gemm_hmma(const TIN* __restrict__ X, const float* __restrict__ Wf,
                            __half* __restrict__ Y, int nrows,
                            int* __restrict__ deg_zero) {
    extern __shared__ __half smemh[];
    __half (*As)[SROW] = (__half(*)[SROW])smemh;
    __half (*Bs)[SROW] = (__half(*)[SROW])(smemh + 128 * SROW);

    int tid = threadIdx.x;
    int rowbase = blockIdx.x * 128;
    int rows = nrows - rowbase; if (rows > 128) rows = 128;

    // fused degree-counter zeroing (replaces a memset launch); grid covers N/128
    if (deg_zero && tid < 128 && rowbase + tid < nrows)
        deg_zero[rowbase + tid] = 0;

    // W: fp32 global -> fp16 smem
    const float4* W4 = (const float4*)Wf;
    #pragma unroll 4
    for (int i = tid; i < 4096; i += 256) {
        int r = i >> 5, c4 = (i & 31) * 4;
        float4 f = W4[i];
        __half2 h0 = __floats2half2_rn(f.x, f.y), h1 = __floats2half2_rn(f.z, f.w);
        uint2 u; u.x = *(unsigned*)&h0; u.y = *(unsigned*)&h1;
        *(uint2*)&Bs[r][c4] = u;
    }
    ldrows(As, X, rowbase, rows, tid);
    __syncthreads();

    int warp = tid >> 5, lane = tid & 31;
    int m0 = warp * 16;
    float acc[16][4];
    #pragma unroll
    for (int i = 0; i < 16; i++)
        #pragma unroll
        for (int j = 0; j < 4; j++) acc[i][j] = 0.f;

    unsigned a_addr = su32(&As[m0 + (lane & 15)][(lane >> 4) * 8]);
    unsigned b_addr = su32(&Bs[lane & 15][(lane >> 4) * 8]);

    #pragma unroll
    for (int ks = 0; ks < 8; ks++) {
        unsigned a0, a1, a2, a3;
        ldsm4(a0, a1, a2, a3, a_addr + ks * 16 * 2);
        #pragma unroll
        for (int pr = 0; pr < 8; pr++) {
            unsigned b0, b1, b2, b3;
            ldsm4t(b0, b1, b2, b3, b_addr + ks * 16 * (SROW * 2) + pr * 16 * 2);
            mma16816(acc[2 * pr + 0], a0, a1, a2, a3, b0, b1);
            mma16816(acc[2 * pr + 1], a0, a1, a2, a3, b2, b3);
        }
    }

    int orow = lane >> 2, ocol = (lane & 3) * 2;
    int r0 = m0 + orow, r1 = r0 + 8;
    bool g0 = (r0 < rows), g1 = (r1 < rows);
    #pragma unroll
    for (int nb = 0; nb < 16; nb++) {
        if (g0) {
            __half2 v = __floats2half2_rn(acc[nb][0], acc[nb][1]);
            *(__half2*)(Y + (size_t)(rowbase + r0) * DIMF + nb * 8 + ocol) = v;
        }
        if (g1) {
            __half2 v = __floats2half2_rn(acc[nb][2], acc[nb][3]);
            *(__half2*)(Y + (size_t)(rowbase + r1) * DIMF + nb * 8 + ocol) = v;
        }
    }
}

// ---------------- agg core: half-warp edge pairing, 16-edge batches ------------
__device__ __forceinline__ void agg_pair(const uint4 q, const float w, float acc[8]) {
    float2 a0 = __half22float2(*(__half2*)&q.x);
    float2 a1 = __half22float2(*(__half2*)&q.y);
    float2 a2 = __half22float2(*(__half2*)&q.z);
    float2 a3 = __half22float2(*(__half2*)&q.w);
    acc[0] = fmaf(w, a0.x, acc[0]); acc[1] = fmaf(w, a0.y, acc[1]);
    acc[2] = fmaf(w, a1.x, acc[2]); acc[3] = fmaf(w, a1.y, acc[3]);
    acc[4] = fmaf(w, a2.x, acc[4]); acc[5] = fmaf(w, a2.y, acc[5]);
    acc[6] = fmaf(w, a3.x, acc[6]); acc[7] = fmaf(w, a3.y, acc[7]);
}

__device__ __forceinline__ void agg_row(const __half* __restrict__ h16,
                                        const unsigned long long* __restrict__ edge,
                                        const float* __restrict__ dinv,
                                        const float* __restrict__ bias,
                                        int v, int e0, int e1, int lane,
                                        float acc[8]) {
    const uint4* h4 = (const uint4*)h16;
    int ep = lane >> 4, cl = lane & 15;
    #pragma unroll
    for (int i = 0; i < 8; i++) acc[i] = 0.f;

    int e = e0;
    for (; e + 16 <= e1; e += 16) {
        unsigned long long p[8];
        uint4 q[8];
        #pragma unroll
        for (int j = 0; j < 8; j++) p[j] = __ldg(edge + e + 2 * j + ep);
        #pragma unroll
        for (int j = 0; j < 8; j++)
            q[j] = __ldg(h4 + (size_t)(unsigned)p[j] * 16 + cl);
        #pragma unroll
        for (int j = 0; j < 8; j++)
            agg_pair(q[j], __uint_as_float((unsigned)(p[j] >> 32)), acc);
    }
    for (; e + 2 <= e1; e += 2) {
        unsigned long long p = __ldg(edge + e + ep);
        uint4 q = __ldg(h4 + (size_t)(unsigned)p * 16 + cl);
        agg_pair(q, __uint_as_float((unsigned)(p >> 32)), acc);
    }
    if (e < e1 && ep == 0) {
        unsigned long long p = __ldg(edge + e);
        uint4 q = __ldg(h4 + (size_t)(unsigned)p * 16 + cl);
        agg_pair(q, __uint_as_float((unsigned)(p >> 32)), acc);
    }

    #pragma unroll
    for (int i = 0; i < 8; i++)
        acc[i] += __shfl_xor_sync(0xffffffffu, acc[i], 16);

    float dv = dinv[v];
    float sw = dv * dv;
    uint4 qs = __ldg(h4 + (size_t)v * 16 + cl);
    float2 s0 = __half22float2(*(__half2*)&qs.x);
    float2 s1 = __half22float2(*(__half2*)&qs.y);
    float2 s2 = __half22float2(*(__half2*)&qs.z);
    float2 s3 = __half22float2(*(__half2*)&qs.w);
    float4 b0 = __ldg((const float4*)bias + cl * 2 + 0);
    float4 b1 = __ldg((const float4*)bias + cl * 2 + 1);
    acc[0] = fmaxf(fmaf(dv, acc[0], fmaf(sw, s0.x, b0.x)), 0.f);
    acc[1] = fmaxf(fmaf(dv, acc[1], fmaf(sw, s0.y, b0.y)), 0.f);
    acc[2] = fmaxf(fmaf(dv, acc[2], fmaf(sw, s1.x, b0.z)), 0.f);
    acc[3] = fmaxf(fmaf(dv, acc[3], fmaf(sw, s1.y, b0.w)), 0.f);
    acc[4] = fmaxf(fmaf(dv, acc[4], fmaf(sw, s2.x, b1.x)), 0.f);
    acc[5] = fmaxf(fmaf(dv, acc[5], fmaf(sw, s2.y, b1.y)), 0.f);
    acc[6] = fmaxf(fmaf(dv, acc[6], fmaf(sw, s3.x, b1.z)), 0.f);
    acc[7] = fmaxf(fmaf(dv, acc[7], fmaf(sw, s3.y, b1.w)), 0.f);
}

// layer-1 aggregation: fp16 out (GEMM2 input)
__global__ void k_agg(const __half* __restrict__ h16, const int* __restrict__ rowptr,
                      const unsigned long long* __restrict__ edge,
                      const float* __restrict__ dinv, const float* __restrict__ bias,
                      __half* __restrict__ out, int N) {
    int v = (blockIdx.x * blockDim.x + threadIdx.x) >> 5;
    int lane = threadIdx.x & 31;
    if (v >= N) return;
    int e0 = __ldg(rowptr + v), e1 = __ldg(rowptr + v + 1);
    float acc[8];
    agg_row(h16, edge, dinv, bias, v, e0, e1, lane, acc);
    if (lane < 16) {
        __half2 h0 = __floats2half2_rn(acc[0], acc[1]);
        __half2 h1 = __floats2half2_rn(acc[2], acc[3]);
        __half2 h2 = __floats2half2_rn(acc[4], acc[5]);
        __half2 h3 = __floats2half2_rn(acc[6], acc[7]);
        uint4 u;
        u.x = *(unsigned*)&h0; u.y = *(unsigned*)&h1;
        u.z = *(unsigned*)&h2; u.w = *(unsigned*)&h3;
        ((uint4*)(out + (size_t)v * DIMF))[lane] = u;
    }
}

// layer-2 aggregation fused with FC(128->40) + log_softmax
__global__ void k_agg_fc(const __half* __restrict__ h16, const int* __restrict__ rowptr,
                         const unsigned long long* __restrict__ edge,
                         const float* __restrict__ dinv, const float* __restrict__ bias,
                         const float* __restrict__ Wfc, const float* __restrict__ bfc,
                         float* __restrict__ out, int N) {
    __shared__ __align__(16) float sh[8][DIMF];
    int w = threadIdx.x >> 5;
    int lane = threadIdx.x & 31;
    int v = blockIdx.x * 8 + w;
    if (v >= N) return;

    int e0 = __ldg(rowptr + v), e1 = __ldg(rowptr + v + 1);
    float acc[8];
    agg_row(h16, edge, dinv, bias, v, e0, e1, lane, acc);
    if (lane < 16) {
        int cl = lane;
        ((float4*)&sh[w][0])[cl * 2 + 0] = make_float4(acc[0], acc[1], acc[2], acc[3]);
        ((float4*)&sh[w][0])[cl * 2 + 1] = make_float4(acc[4], acc[5], acc[6], acc[7]);
    }
    __syncwarp();

    float acc0 = 0.f, acc1 = 0.f;
    bool hi = (lane < 8);
    #pragma unroll 4
    for (int k4 = 0; k4 < 32; k4++) {
        float4 xv = ((const float4*)&sh[w][0])[k4];
        int k = k4 * 4;
        acc0 = fmaf(xv.x, __ldg(Wfc + (k + 0) * 40 + lane), acc0);
        acc0 = fmaf(xv.y, __ldg(Wfc + (k + 1) * 40 + lane), acc0);
        acc0 = fmaf(xv.z, __ldg(Wfc + (k + 2) * 40 + lane), acc0);
        acc0 = fmaf(xv.w, __ldg(Wfc + (k + 3) * 40 + lane), acc0);
        if (hi) {
            acc1 = fmaf(xv.x, __ldg(Wfc + (k + 0) * 40 + 32 + lane), acc1);
            acc1 = fmaf(xv.y, __ldg(Wfc + (k + 1) * 40 + 32 + lane), acc1);
            acc1 = fmaf(xv.z, __ldg(Wfc + (k + 2) * 40 + 32 + lane), acc1);
            acc1 = fmaf(xv.w, __ldg(Wfc + (k + 3) * 40 + 32 + lane), acc1);
        }
    }
    acc0 += __ldg(bfc + lane);
    if (hi) acc1 += __ldg(bfc + 32 + lane);

    float m = hi ? fmaxf(acc0, acc1) : acc0;
    #pragma unroll
    for (int o2 = 16; o2; o2 >>= 1) m = fmaxf(m, __shfl_xor_sync(0xffffffffu, m, o2));
    float s = expf(acc0 - m) + (hi ? expf(acc1 - m) : 0.f);
    #pragma unroll
    for (int o2 = 16; o2; o2 >>= 1) s += __shfl_xor_sync(0xffffffffu, s, o2);
    float lse = logf(s) + m;

    out[(size_t)v * 40 + lane] = acc0 - lse;
    if (hi) out[(size_t)v * 40 + 32 + lane] = acc1 - lse;
}

// ---------------- host launcher ----------------------------------------------
extern "C" void kernel_launch(void* const* d_in, const int* in_sizes, int n_in,
                              void* d_out, int out_size) {
    const float* x    = (const float*)d_in[0];
    const float* W1   = (const float*)d_in[1];
    const float* b1   = (const float*)d_in[2];
    const float* W2   = (const float*)d_in[3];
    const float* b2   = (const float*)d_in[4];
    const float* Wfc  = (const float*)d_in[5];
    const float* bfc  = (const float*)d_in[6];
    const int*   eidx = (const int*)d_in[7];
    float* out = (float*)d_out;

    int N = in_sizes[0] / DIMF;
    int E = in_sizes[7] / 2;
    if (N > NMAX) N = NMAX;
    if (E > EMAX) E = EMAX;

    __half *ph16, *pb16;
    float* pdinv;
    int *pdeg, *prow, *pbs;
    unsigned long long* pedge;
    cudaGetSymbolAddress((void**)&ph16,  g_h16);
    cudaGetSymbolAddress((void**)&pb16,  g_b16);
    cudaGetSymbolAddress((void**)&pdeg,  g_deg);
    cudaGetSymbolAddress((void**)&pdinv, g_dinv);
    cudaGetSymbolAddress((void**)&prow,  g_rowptr);
    cudaGetSymbolAddress((void**)&pbs,   g_bsums);
    cudaGetSymbolAddress((void**)&pedge, g_edge);

    int smem_gemm = 2 * 128 * SROW * (int)sizeof(__half);   // 69632 B
    cudaFuncSetAttribute(k_gemm_hmma<float>,
                         cudaFuncAttributeMaxDynamicSharedMemorySize, smem_gemm);
    cudaFuncSetAttribute(k_gemm_hmma<__half>,
                         cudaFuncAttributeMaxDynamicSharedMemorySize, smem_gemm);

    const int* srcp = eidx;
    const int* dstp = eidx + E;

    int gb = (N + 127) / 128;
    int ab = (N * 32 + 255) / 256;
    int nb = (N + 1023) / 1024;

    // single stream, deterministic launch order (k_agg = 6th launch -> ncu -s 5)
    // 1: GEMM1 (converts W1 in-block, zeroes degree counters)
    k_gemm_hmma<float><<<gb, 256, smem_gemm>>>(x, W1, ph16, N, pdeg);
    // 2-5: CSR build
    k_hist<<<(E + 255) / 256, 256>>>(dstp, E, pdeg);
    k_scan1<<<nb, 256>>>(pdeg, prow, pbs, pdinv, N);
    k_scan23<<<nb, 1024>>>(prow, pbs, pdeg, N, E);
    k_scatter<<<(E + 255) / 256, 256>>>(srcp, dstp, E, prow, pdeg, pdinv, pedge);
    // 6: layer-1 aggregation  <-- profiled by ncu -s 5 -c 1
    k_agg<<<ab, 256>>>(ph16, prow, pedge, pdinv, b1, pb16, N);
    // 7: GEMM2 (converts W2 in-block)
    k_gemm_hmma<__half><<<gb, 256, smem_gemm>>>(pb16, W2, ph16, N, nullptr);
    // 8: layer-2 agg + FC + log_softmax
    k_agg_fc<<<(N + 7) / 8, 256>>>(ph16, prow, pedge, pdinv, b2, Wfc, bfc, out, N);
}

// round 17
// speedup vs baseline: 1.1825x; 1.0087x over previous
#include <cuda_runtime.h>
#include <cuda_fp16.h>
#include <math.h>

#define NMAX 100000
#define EMAX 3200000
#define DIMF 128
#define SROW (DIMF + 8)   // padded smem row (halves)

// ---------------- scratch ----------------------------------------------------
__device__ __align__(16) __half g_h16[(size_t)NMAX * DIMF];  // GEMM out (gathered)
__device__ __align__(16) __half g_b16[(size_t)NMAX * DIMF];  // agg1 out (GEMM2 in)
__device__ __align__(16) __half g_W1h[DIMF * DIMF];
__device__ __align__(16) __half g_W2h[DIMF * DIMF];
__device__ __align__(16) int    g_deg[NMAX];
__device__ __align__(16) float  g_dinv[NMAX];
__device__ __align__(16) int    g_rowptr[NMAX + 1];
__device__ __align__(16) int    g_bsums[512];
__device__ __align__(16) unsigned long long g_edge[EMAX];    // {ws_bits:32 | col:32}

// ---------------- mma / ldmatrix helpers --------------------------------------
__device__ __forceinline__ unsigned su32(const void* p) {
    return (unsigned)__cvta_generic_to_shared(p);
}
__device__ __forceinline__ void ldsm4(unsigned& r0, unsigned& r1, unsigned& r2,
                                      unsigned& r3, unsigned addr) {
    asm volatile("ldmatrix.sync.aligned.m8n8.x4.shared.b16 {%0,%1,%2,%3}, [%4];"
                 : "=r"(r0), "=r"(r1), "=r"(r2), "=r"(r3) : "r"(addr));
}
__device__ __forceinline__ void ldsm4t(unsigned& r0, unsigned& r1, unsigned& r2,
                                       unsigned& r3, unsigned addr) {
    asm volatile("ldmatrix.sync.aligned.m8n8.x4.trans.shared.b16 {%0,%1,%2,%3}, [%4];"
                 : "=r"(r0), "=r"(r1), "=r"(r2), "=r"(r3) : "r"(addr));
}
__device__ __forceinline__ void mma16816(float* d, unsigned a0, unsigned a1,
                                         unsigned a2, unsigned a3,
                                         unsigned b0, unsigned b1) {
    asm volatile("mma.sync.aligned.m16n8k16.row.col.f32.f16.f16.f32 "
                 "{%0,%1,%2,%3},{%4,%5,%6,%7},{%8,%9},{%0,%1,%2,%3};"
                 : "+f"(d[0]), "+f"(d[1]), "+f"(d[2]), "+f"(d[3])
                 : "r"(a0), "r"(a1), "r"(a2), "r"(a3), "r"(b0), "r"(b1));
}

// ---------------- CSR build ----------------------------------------------------
__global__ void k_hist(const int* __restrict__ dst, int E, int* __restrict__ deg) {
    int e = blockIdx.x * blockDim.x + threadIdx.x;
    if (e < E) atomicAdd(&deg[dst[e]], 1);
}
__global__ void k_scan1(const int* __restrict__ in, int* __restrict__ out,
                        int* __restrict__ bsums, float* __restrict__ dinv, int n) {
    __shared__ int wsum[8];
    int tid  = threadIdx.x;
    int base = blockIdx.x * 1024 + tid * 4;
    int v0 = 0, v1 = 0, v2 = 0, v3 = 0;
    if (base + 0 < n) v0 = in[base + 0];
    if (base + 1 < n) v1 = in[base + 1];
    if (base + 2 < n) v2 = in[base + 2];
    if (base + 3 < n) v3 = in[base + 3];
    if (base + 0 < n) dinv[base + 0] = rsqrtf((float)(v0 + 1));
    if (base + 1 < n) dinv[base + 1] = rsqrtf((float)(v1 + 1));
    if (base + 2 < n) dinv[base + 2] = rsqrtf((float)(v2 + 1));
    if (base + 3 < n) dinv[base + 3] = rsqrtf((float)(v3 + 1));
    int s = v0 + v1 + v2 + v3;
    int lane = tid & 31, wid = tid >> 5;
    int inc = s;
    #pragma unroll
    for (int o = 1; o < 32; o <<= 1) {
        int t = __shfl_up_sync(0xffffffffu, inc, o);
        if (lane >= o) inc += t;
    }
    if (lane == 31) wsum[wid] = inc;
    __syncthreads();
    if (tid == 0) {
        int run = 0;
        #pragma unroll
        for (int i = 0; i < 8; i++) { int t = wsum[i]; wsum[i] = run; run += t; }
        bsums[blockIdx.x] = run;
    }
    __syncthreads();
    int ex = wsum[wid] + inc - s;
    if (base + 0 < n) out[base + 0] = ex;
    if (base + 1 < n) out[base + 1] = ex + v0;
    if (base + 2 < n) out[base + 2] = ex + v0 + v1;
    if (base + 3 < n) out[base + 3] = ex + v0 + v1 + v2;
}
// merged scan2+scan3: each block reduces bsums[0..blockIdx-1] in-block (nb<=98),
// adds offset to its rowptr chunk, zeroes fill counters.
__global__ void k_scan23(int* __restrict__ rowptr, const int* __restrict__ bsums,
                         int* __restrict__ fill, int n, int E) {
    __shared__ int wsum[32];
    int t = threadIdx.x;   // blockDim = 1024
    int b = blockIdx.x;
    int val = (t < b) ? bsums[t] : 0;   // nb <= 98 < 1024
    int lane = t & 31, wid = t >> 5;
    #pragma unroll
    for (int o = 16; o; o >>= 1) val += __shfl_xor_sync(0xffffffffu, val, o);
    if (lane == 0) wsum[wid] = val;
    __syncthreads();
    if (t == 0) {
        int tot = 0;
        #pragma unroll
        for (int i = 0; i < 32; i++) tot += wsum[i];
        wsum[0] = tot;
    }
    __syncthreads();
    int off = wsum[0];
    int i = b * 1024 + t;
    if (i < n) { rowptr[i] += off; fill[i] = 0; }
    if (i == 0) rowptr[n] = E;
}
__global__ void k_scatter(const int* __restrict__ srcp, const int* __restrict__ dstp,
                          int E, const int* __restrict__ rowptr, int* __restrict__ fill,
                          const float* __restrict__ dinv,
                          unsigned long long* __restrict__ edge) {
    int e = blockIdx.x * blockDim.x + threadIdx.x;
    if (e >= E) return;
    int s = srcp[e];
    int d = dstp[e];
    int pos = rowptr[d] + atomicAdd(&fill[d], 1);
    unsigned long long w = (unsigned long long)__float_as_uint(dinv[s]);
    edge[pos] = (w << 32) | (unsigned int)s;
}

// ---------------- weight convert ------------------------------------------------
__global__ void k_cvtW(const float* __restrict__ W1, const float* __restrict__ W2,
                       __half* __restrict__ W1h, __half* __restrict__ W2h) {
    int i = blockIdx.x * blockDim.x + threadIdx.x;
    if (i < DIMF * DIMF) {
        W1h[i] = __float2half(W1[i]);
        W2h[i] = __float2half(W2[i]);
    }
}

// ---------------- HMMA GEMM: Y[nrows,128] = X[nrows,128] @ W[128,128] -----------
__device__ __forceinline__ void ldrows(__half (*As)[SROW], const float* X,
                                       int rowbase, int rows, int tid) {
    for (int i = tid; i < rows * 16; i += 256) {
        int r = i >> 4, c8 = (i & 15) * 8;
        const float4* p = (const float4*)(X + (size_t)(rowbase + r) * DIMF + c8);
        float4 f0 = p[0], f1 = p[1];
        __half2 h0 = __floats2half2_rn(f0.x, f0.y), h1 = __floats2half2_rn(f0.z, f0.w);
        __half2 h2 = __floats2half2_rn(f1.x, f1.y), h3 = __floats2half2_rn(f1.z, f1.w);
        uint4 u;
        u.x = *(unsigned*)&h0; u.y = *(unsigned*)&h1;
        u.z = *(unsigned*)&h2; u.w = *(unsigned*)&h3;
        *(uint4*)&As[r][c8] = u;
    }
}
__device__ __forceinline__ void ldrows(__half (*As)[SROW], const __half* X,
                                       int rowbase, int rows, int tid) {
    for (int i = tid; i < rows * 16; i += 256) {
        int r = i >> 4, c8 = (i & 15) * 8;
        *(uint4*)&As[r][c8] = *(const uint4*)(X + (size_t)(rowbase + r) * DIMF + c8);
    }
}

template <typename TIN>
__global__ void k_gemm_hmma(const TIN* __restrict__ X, const __half* __restrict__ Wh,
                            __half* __restrict__ Y, int nrows) {
    extern __shared__ __half smemh[];
    __half (*As)[SROW] = (__half(*)[SROW])smemh;
    __half (*Bs)[SROW] = (__half(*)[SROW])(smemh + 128 * SROW);

    int tid = threadIdx.x;
    int rowbase = blockIdx.x * 128;
    int rows = nrows - rowbase; if (rows > 128) rows = 128;

    #pragma unroll 4
    for (int i = tid; i < 128 * 16; i += 256) {
        int r = i >> 4, c8 = (i & 15) * 8;
        *(uint4*)&Bs[r][c8] = *(const uint4*)(Wh + r * DIMF + c8);
    }
    ldrows(As, X, rowbase, rows, tid);
    __syncthreads();

    int warp = tid >> 5, lane = tid & 31;
    int m0 = warp * 16;
    float acc[16][4];
    #pragma unroll
    for (int i = 0; i < 16; i++)
        #pragma unroll
        for (int j = 0; j < 4; j++) acc[i][j] = 0.f;

    unsigned a_addr = su32(&As[m0 + (lane & 15)][(lane >> 4) * 8]);
    unsigned b_addr = su32(&Bs[lane & 15][(lane >> 4) * 8]);

    #pragma unroll
    for (int ks = 0; ks < 8; ks++) {
        unsigned a0, a1, a2, a3;
        ldsm4(a0, a1, a2, a3, a_addr + ks * 16 * 2);
        #pragma unroll
        for (int pr = 0; pr < 8; pr++) {
            unsigned b0, b1, b2, b3;
            ldsm4t(b0, b1, b2, b3, b_addr + ks * 16 * (SROW * 2) + pr * 16 * 2);
            mma16816(acc[2 * pr + 0], a0, a1, a2, a3, b0, b1);
            mma16816(acc[2 * pr + 1], a0, a1, a2, a3, b2, b3);
        }
    }

    int orow = lane >> 2, ocol = (lane & 3) * 2;
    int r0 = m0 + orow, r1 = r0 + 8;
    bool g0 = (r0 < rows), g1 = (r1 < rows);
    #pragma unroll
    for (int nb = 0; nb < 16; nb++) {
        if (g0) {
            __half2 v = __floats2half2_rn(acc[nb][0], acc[nb][1]);
            *(__half2*)(Y + (size_t)(rowbase + r0) * DIMF + nb * 8 + ocol) = v;
        }
        if (g1) {
            __half2 v = __floats2half2_rn(acc[nb][2], acc[nb][3]);
            *(__half2*)(Y + (size_t)(rowbase + r1) * DIMF + nb * 8 + ocol) = v;
        }
    }
}

// ---------------- agg core: half-warp edge pairing, 16-edge batches ------------
__device__ __forceinline__ void agg_pair(const uint4 q, const float w, float acc[8]) {
    float2 a0 = __half22float2(*(__half2*)&q.x);
    float2 a1 = __half22float2(*(__half2*)&q.y);
    float2 a2 = __half22float2(*(__half2*)&q.z);
    float2 a3 = __half22float2(*(__half2*)&q.w);
    acc[0] = fmaf(w, a0.x, acc[0]); acc[1] = fmaf(w, a0.y, acc[1]);
    acc[2] = fmaf(w, a1.x, acc[2]); acc[3] = fmaf(w, a1.y, acc[3]);
    acc[4] = fmaf(w, a2.x, acc[4]); acc[5] = fmaf(w, a2.y, acc[5]);
    acc[6] = fmaf(w, a3.x, acc[6]); acc[7] = fmaf(w, a3.y, acc[7]);
}

__device__ __forceinline__ void agg_row(const __half* __restrict__ h16,
                                        const unsigned long long* __restrict__ edge,
                                        const float* __restrict__ dinv,
                                        const float* __restrict__ bias,
                                        int v, int e0, int e1, int lane,
                                        float acc[8]) {
    const uint4* h4 = (const uint4*)h16;
    int ep = lane >> 4, cl = lane & 15;
    #pragma unroll
    for (int i = 0; i < 8; i++) acc[i] = 0.f;

    int e = e0;
    for (; e + 16 <= e1; e += 16) {
        unsigned long long p[8];
        uint4 q[8];
        #pragma unroll
        for (int j = 0; j < 8; j++) p[j] = __ldg(edge + e + 2 * j + ep);
        #pragma unroll
        for (int j = 0; j < 8; j++)
            q[j] = __ldg(h4 + (size_t)(unsigned)p[j] * 16 + cl);
        #pragma unroll
        for (int j = 0; j < 8; j++)
            agg_pair(q[j], __uint_as_float((unsigned)(p[j] >> 32)), acc);
    }
    for (; e + 2 <= e1; e += 2) {
        unsigned long long p = __ldg(edge + e + ep);
        uint4 q = __ldg(h4 + (size_t)(unsigned)p * 16 + cl);
        agg_pair(q, __uint_as_float((unsigned)(p >> 32)), acc);
    }
    if (e < e1 && ep == 0) {
        unsigned long long p = __ldg(edge + e);
        uint4 q = __ldg(h4 + (size_t)(unsigned)p * 16 + cl);
        agg_pair(q, __uint_as_float((unsigned)(p >> 32)), acc);
    }

    #pragma unroll
    for (int i = 0; i < 8; i++)
        acc[i] += __shfl_xor_sync(0xffffffffu, acc[i], 16);

    float dv = dinv[v];
    float sw = dv * dv;
    uint4 qs = __ldg(h4 + (size_t)v * 16 + cl);
    float2 s0 = __half22float2(*(__half2*)&qs.x);
    float2 s1 = __half22float2(*(__half2*)&qs.y);
    float2 s2 = __half22float2(*(__half2*)&qs.z);
    float2 s3 = __half22float2(*(__half2*)&qs.w);
    float4 b0 = __ldg((const float4*)bias + cl * 2 + 0);
    float4 b1 = __ldg((const float4*)bias + cl * 2 + 1);
    acc[0] = fmaxf(fmaf(dv, acc[0], fmaf(sw, s0.x, b0.x)), 0.f);
    acc[1] = fmaxf(fmaf(dv, acc[1], fmaf(sw, s0.y, b0.y)), 0.f);
    acc[2] = fmaxf(fmaf(dv, acc[2], fmaf(sw, s1.x, b0.z)), 0.f);
    acc[3] = fmaxf(fmaf(dv, acc[3], fmaf(sw, s1.y, b0.w)), 0.f);
    acc[4] = fmaxf(fmaf(dv, acc[4], fmaf(sw, s2.x, b1.x)), 0.f);
    acc[5] = fmaxf(fmaf(dv, acc[5], fmaf(sw, s2.y, b1.y)), 0.f);
    acc[6] = fmaxf(fmaf(dv, acc[6], fmaf(sw, s3.x, b1.z)), 0.f);
    acc[7] = fmaxf(fmaf(dv, acc[7], fmaf(sw, s3.y, b1.w)), 0.f);
}

// layer-1 aggregation: fp16 out (GEMM2 input)
__global__ void k_agg(const __half* __restrict__ h16, const int* __restrict__ rowptr,
                      const unsigned long long* __restrict__ edge,
                      const float* __restrict__ dinv, const float* __restrict__ bias,
                      __half* __restrict__ out, int N) {
    int v = (blockIdx.x * blockDim.x + threadIdx.x) >> 5;
    int lane = threadIdx.x & 31;
    if (v >= N) return;
    int e0 = __ldg(rowptr + v), e1 = __ldg(rowptr + v + 1);
    float acc[8];
    agg_row(h16, edge, dinv, bias, v, e0, e1, lane, acc);
    if (lane < 16) {
        __half2 h0 = __floats2half2_rn(acc[0], acc[1]);
        __half2 h1 = __floats2half2_rn(acc[2], acc[3]);
        __half2 h2 = __floats2half2_rn(acc[4], acc[5]);
        __half2 h3 = __floats2half2_rn(acc[6], acc[7]);
        uint4 u;
        u.x = *(unsigned*)&h0; u.y = *(unsigned*)&h1;
        u.z = *(unsigned*)&h2; u.w = *(unsigned*)&h3;
        ((uint4*)(out + (size_t)v * DIMF))[lane] = u;
    }
}

// layer-2 aggregation fused with FC(128->40) + log_softmax
__global__ void k_agg_fc(const __half* __restrict__ h16, const int* __restrict__ rowptr,
                         const unsigned long long* __restrict__ edge,
                         const float* __restrict__ dinv, const float* __restrict__ bias,
                         const float* __restrict__ Wfc, const float* __restrict__ bfc,
                         float* __restrict__ out, int N) {
    __shared__ __align__(16) float sh[8][DIMF];
    int w = threadIdx.x >> 5;
    int lane = threadIdx.x & 31;
    int v = blockIdx.x * 8 + w;
    if (v >= N) return;

    int e0 = __ldg(rowptr + v), e1 = __ldg(rowptr + v + 1);
    float acc[8];
    agg_row(h16, edge, dinv, bias, v, e0, e1, lane, acc);
    if (lane < 16) {
        int cl = lane;
        ((float4*)&sh[w][0])[cl * 2 + 0] = make_float4(acc[0], acc[1], acc[2], acc[3]);
        ((float4*)&sh[w][0])[cl * 2 + 1] = make_float4(acc[4], acc[5], acc[6], acc[7]);
    }
    __syncwarp();

    float acc0 = 0.f, acc1 = 0.f;
    bool hi = (lane < 8);
    #pragma unroll 4
    for (int k4 = 0; k4 < 32; k4++) {
        float4 xv = ((const float4*)&sh[w][0])[k4];
        int k = k4 * 4;
        acc0 = fmaf(xv.x, __ldg(Wfc + (k + 0) * 40 + lane), acc0);
        acc0 = fmaf(xv.y, __ldg(Wfc + (k + 1) * 40 + lane), acc0);
        acc0 = fmaf(xv.z, __ldg(Wfc + (k + 2) * 40 + lane), acc0);
        acc0 = fmaf(xv.w, __ldg(Wfc + (k + 3) * 40 + lane), acc0);
        if (hi) {
            acc1 = fmaf(xv.x, __ldg(Wfc + (k + 0) * 40 + 32 + lane), acc1);
            acc1 = fmaf(xv.y, __ldg(Wfc + (k + 1) * 40 + 32 + lane), acc1);
            acc1 = fmaf(xv.z, __ldg(Wfc + (k + 2) * 40 + 32 + lane), acc1);
            acc1 = fmaf(xv.w, __ldg(Wfc + (k + 3) * 40 + 32 + lane), acc1);
        }
    }
    acc0 += __ldg(bfc + lane);
    if (hi) acc1 += __ldg(bfc + 32 + lane);

    float m = hi ? fmaxf(acc0, acc1) : acc0;
    #pragma unroll
    for (int o2 = 16; o2; o2 >>= 1) m = fmaxf(m, __shfl_xor_sync(0xffffffffu, m, o2));
    float s = expf(acc0 - m) + (hi ? expf(acc1 - m) : 0.f);
    #pragma unroll
    for (int o2 = 16; o2; o2 >>= 1) s += __shfl_xor_sync(0xffffffffu, s, o2);
    float lse = logf(s) + m;

    out[(size_t)v * 40 + lane] = acc0 - lse;
    if (hi) out[(size_t)v * 40 + 32 + lane] = acc1 - lse;
}

// ---------------- host launcher ----------------------------------------------
extern "C" void kernel_launch(void* const* d_in, const int* in_sizes, int n_in,
                              void* d_out, int out_size) {
    const float* x    = (const float*)d_in[0];
    const float* W1   = (const float*)d_in[1];
    const float* b1   = (const float*)d_in[2];
    const float* W2   = (const float*)d_in[3];
    const float* b2   = (const float*)d_in[4];
    const float* Wfc  = (const float*)d_in[5];
    const float* bfc  = (const float*)d_in[6];
    const int*   eidx = (const int*)d_in[7];
    float* out = (float*)d_out;

    int N = in_sizes[0] / DIMF;
    int E = in_sizes[7] / 2;
    if (N > NMAX) N = NMAX;
    if (E > EMAX) E = EMAX;

    __half *ph16, *pb16, *pW1h, *pW2h;
    float* pdinv;
    int *pdeg, *prow, *pbs;
    unsigned long long* pedge;
    cudaGetSymbolAddress((void**)&ph16,  g_h16);
    cudaGetSymbolAddress((void**)&pb16,  g_b16);
    cudaGetSymbolAddress((void**)&pW1h,  g_W1h);
    cudaGetSymbolAddress((void**)&pW2h,  g_W2h);
    cudaGetSymbolAddress((void**)&pdeg,  g_deg);
    cudaGetSymbolAddress((void**)&pdinv, g_dinv);
    cudaGetSymbolAddress((void**)&prow,  g_rowptr);
    cudaGetSymbolAddress((void**)&pbs,   g_bsums);
    cudaGetSymbolAddress((void**)&pedge, g_edge);

    int smem_gemm = 2 * 128 * SROW * (int)sizeof(__half);   // 69632 B
    cudaFuncSetAttribute(k_gemm_hmma<float>,
                         cudaFuncAttributeMaxDynamicSharedMemorySize, smem_gemm);
    cudaFuncSetAttribute(k_gemm_hmma<__half>,
                         cudaFuncAttributeMaxDynamicSharedMemorySize, smem_gemm);

    static cudaStream_t s2 = nullptr;
    static cudaEvent_t evFork = nullptr, evJoin = nullptr;
    if (s2 == nullptr) {
        cudaStreamCreateWithFlags(&s2, cudaStreamNonBlocking);
        cudaEventCreateWithFlags(&evFork, cudaEventDisableTiming);
        cudaEventCreateWithFlags(&evJoin, cudaEventDisableTiming);
    }

    const int* srcp = eidx;
    const int* dstp = eidx + E;

    int gb = (N + 127) / 128;
    int ab = (N * 32 + 255) / 256;
    int nb = (N + 1023) / 1024;

    // ---- fork: cvtW + GEMM1 on side stream, CSR chain on main stream ----
    cudaEventRecord(evFork, 0);
    cudaStreamWaitEvent(s2, evFork, 0);
    k_cvtW<<<(DIMF * DIMF + 255) / 256, 256, 0, s2>>>(W1, W2, pW1h, pW2h);
    k_gemm_hmma<float><<<gb, 256, smem_gemm, s2>>>(x, pW1h, ph16, N);
    cudaEventRecord(evJoin, s2);

    // main stream: CSR build (merged scan2+scan3)
    cudaMemsetAsync(pdeg, 0, (size_t)N * sizeof(int));
    k_hist<<<(E + 255) / 256, 256>>>(dstp, E, pdeg);
    k_scan1<<<nb, 256>>>(pdeg, prow, pbs, pdinv, N);
    k_scan23<<<nb, 1024>>>(prow, pbs, pdeg, N, E);
    k_scatter<<<(E + 255) / 256, 256>>>(srcp, dstp, E, prow, pdeg, pdinv, pedge);

    // join: agg1 needs GEMM1 output + CSR
    cudaStreamWaitEvent(0, evJoin, 0);
    k_agg<<<ab, 256>>>(ph16, prow, pedge, pdinv, b1, pb16, N);

    // layer 2 + fused agg/FC/log_softmax
    k_gemm_hmma<__half><<<gb, 256, smem_gemm>>>(pb16, pW2h, ph16, N);
    k_agg_fc<<<(N + 7) / 8, 256>>>(ph16, prow, pedge, pdinv, b2, Wfc, bfc, out, N);
}